// round 11
// baseline (speedup 1.0000x reference)
#include <cuda_runtime.h>
#include <cuda_bf16.h>

#define Bb 64
#define Tt 64
#define Hh 1024
#define Vv 32000
#define Ee 512
#define WHH (4 * Hh * Hh)

// ---------------- scratch (static device memory; no allocation) ----------------
__device__ float g_xbuf[Tt * Bb * Ee];
__device__ float g_h[8 * Bb * Hh];
__device__ float g_c[4 * Bb * Hh];
__device__ float g_zpre[Tt * Bb * 4 * Hh];
__device__ __nv_bfloat16 g_Ahi[4096 * 1024];
__device__ __nv_bfloat16 g_Alo[4096 * 1024];
__device__ __nv_bfloat16 g_B1hi[4096 * 512];
__device__ __nv_bfloat16 g_B1lo[4096 * 512];
__device__ __nv_bfloat16 g_Bhi[(size_t)Vv * 1024];
__device__ __nv_bfloat16 g_Blo[(size_t)Vv * 1024];
__device__ __nv_bfloat16 g_hsp_hi[8 * Bb * Hh];
__device__ __nv_bfloat16 g_hsp_lo[8 * Bb * Hh];
__device__ __nv_bfloat16 g_Wsp_hi[3 * WHH];
__device__ __nv_bfloat16 g_Wsp_lo[3 * WHH];
__device__ __nv_bfloat16 g_Usp_hi[4 * WHH];
__device__ __nv_bfloat16 g_Usp_lo[4 * WHH];

struct CellArgs {
    const float* b[4];
};

// ---------------- cp.async / ldmatrix / mma helpers -----------------------------
__device__ __forceinline__ void cp16(void* smem_dst, const void* gsrc) {
    unsigned s = (unsigned)__cvta_generic_to_shared(smem_dst);
    asm volatile("cp.async.cg.shared.global [%0], [%1], 16;\n" :: "r"(s), "l"(gsrc));
}
__device__ __forceinline__ void cp_commit() {
    asm volatile("cp.async.commit_group;\n" ::: "memory");
}
__device__ __forceinline__ void cp_wait0() {
    asm volatile("cp.async.wait_group 0;\n" ::: "memory");
}
__device__ __forceinline__ void barw(int id) {
    asm volatile("bar.sync %0, 128;" :: "r"(id) : "memory");
}

__device__ __forceinline__ void ldsm_x4(unsigned& r0, unsigned& r1, unsigned& r2,
                                        unsigned& r3, unsigned addr) {
    asm volatile("ldmatrix.sync.aligned.m8n8.x4.shared.b16 {%0,%1,%2,%3}, [%4];"
                 : "=r"(r0), "=r"(r1), "=r"(r2), "=r"(r3) : "r"(addr));
}
__device__ __forceinline__ void ldsm_x2(unsigned& r0, unsigned& r1, unsigned addr) {
    asm volatile("ldmatrix.sync.aligned.m8n8.x2.shared.b16 {%0,%1}, [%2];"
                 : "=r"(r0), "=r"(r1) : "r"(addr));
}

__device__ __forceinline__ void mma16816(float c[4],
                                         unsigned a0, unsigned a1, unsigned a2, unsigned a3,
                                         unsigned b0, unsigned b1) {
    asm volatile(
        "mma.sync.aligned.m16n8k16.row.col.f32.bf16.bf16.f32 "
        "{%0,%1,%2,%3}, {%4,%5,%6,%7}, {%8,%9}, {%0,%1,%2,%3};"
        : "+f"(c[0]), "+f"(c[1]), "+f"(c[2]), "+f"(c[3])
        : "r"(a0), "r"(a1), "r"(a2), "r"(a3), "r"(b0), "r"(b1));
}

// ---------------- embedding lookup ---------------------------------------------
__global__ __launch_bounds__(256) void embed_k(const int* __restrict__ tok,
                                               const float* __restrict__ emb) {
    int idx = blockIdx.x * 256 + threadIdx.x;
    int e  = idx & (Ee - 1);
    int bt = idx >> 9;
    int b  = bt & (Bb - 1);
    int t  = bt >> 6;
    g_xbuf[idx] = emb[(size_t)tok[b * Tt + t] * Ee + e];
}

// ---------------- fp32 -> (hi, lo) bf16 split ----------------------------------
__global__ __launch_bounds__(256) void split_k(const float* __restrict__ src,
                                               __nv_bfloat16* __restrict__ hi,
                                               __nv_bfloat16* __restrict__ lo, int n) {
    int i = blockIdx.x * 256 + threadIdx.x;
    if (i < n) {
        float x = src[i];
        __nv_bfloat16 h = __float2bfloat16(x);
        hi[i] = h;
        lo[i] = __float2bfloat16(x - __bfloat162float(h));
    }
}

// ---------------- split initial h states ---------------------------------------
__global__ __launch_bounds__(256) void hinit_split_k() {
    int i = blockIdx.x * 256 + threadIdx.x;
    int l = i >> 16;
    int r = i & 65535;
    size_t o = ((size_t)(l * 2)) * (Bb * Hh) + r;
    float x = g_h[o];
    __nv_bfloat16 h = __float2bfloat16(x);
    g_hsp_hi[o] = h;
    g_hsp_lo[o] = __float2bfloat16(x - __bfloat162float(h));
}

// ---------------- transpose + split: src[K][N] -> hi/lo [N][K] ------------------
__global__ __launch_bounds__(256) void tsplit_k(const float* __restrict__ src,
                                                __nv_bfloat16* __restrict__ hi,
                                                __nv_bfloat16* __restrict__ lo,
                                                int K, int N) {
    __shared__ float tile[32][33];
    int k0 = blockIdx.x * 32, n0 = blockIdx.y * 32;
    int tx = threadIdx.x & 31, ty = threadIdx.x >> 5;
#pragma unroll
    for (int j = 0; j < 32; j += 8)
        tile[ty + j][tx] = src[(size_t)(k0 + ty + j) * N + n0 + tx];
    __syncthreads();
#pragma unroll
    for (int j = 0; j < 32; j += 8) {
        float x = tile[tx][ty + j];
        __nv_bfloat16 h = __float2bfloat16(x);
        size_t o = (size_t)(n0 + ty + j) * K + k0 + tx;
        hi[o] = h;
        lo[o] = __float2bfloat16(x - __bfloat162float(h));
    }
}

// ---------------- split-bf16 tensor-core GEMM, fused 3-pass + ldmatrix ----------
// Single __syncthreads per iteration: wait -> sync -> issue(i+1) -> compute(i).
#define FSTG (128 * 40)
__global__ __launch_bounds__(256) void mma_gemm_k(
    const __nv_bfloat16* __restrict__ Ahi, const __nv_bfloat16* __restrict__ Alo,
    const __nv_bfloat16* __restrict__ Bhi, const __nv_bfloat16* __restrict__ Blo,
    const float* __restrict__ bias,
    float* __restrict__ out, int K, int N, int perm, int rowbase)
{
    extern __shared__ __nv_bfloat16 fsm[];
    const unsigned sbase = (unsigned)__cvta_generic_to_shared(fsm);

    const int tid  = threadIdx.x;
    const int row0 = rowbase + blockIdx.x * 128;
    const int col0 = blockIdx.y * 128;
    const int wid  = tid >> 5, lane = tid & 31;
    const int wm   = wid >> 2;
    const int wn   = wid & 3;
    const int g    = lane >> 2, tg = lane & 3;

    const int la_row = lane & 15;
    const int la_k   = (lane >> 4) * 8;
    const int lb_row = lane & 7;
    const int lb_k   = ((lane >> 3) & 1) * 8;

    const int niter = K >> 5;

    float acc[4][4][4];
#pragma unroll
    for (int im = 0; im < 4; im++)
#pragma unroll
        for (int in_ = 0; in_ < 4; in_++)
#pragma unroll
            for (int q = 0; q < 4; q++) acc[im][in_][q] = 0.f;

    const int ca  = tid * 2;
    const int ar0 = ca >> 2,       ao0 = (ca & 3) * 8;
    const int ar1 = (ca + 1) >> 2, ao1 = ((ca + 1) & 3) * 8;

    auto issue = [&](int it, int buf) {
        int k0 = it * 32;
        __nv_bfloat16* base = fsm + buf * 4 * FSTG;
        cp16(base + ar0 * 40 + ao0,            Ahi + (size_t)(row0 + ar0) * K + k0 + ao0);
        cp16(base + ar1 * 40 + ao1,            Ahi + (size_t)(row0 + ar1) * K + k0 + ao1);
        cp16(base + FSTG + ar0 * 40 + ao0,     Alo + (size_t)(row0 + ar0) * K + k0 + ao0);
        cp16(base + FSTG + ar1 * 40 + ao1,     Alo + (size_t)(row0 + ar1) * K + k0 + ao1);
        cp16(base + 2 * FSTG + ar0 * 40 + ao0, Bhi + (size_t)(col0 + ar0) * K + k0 + ao0);
        cp16(base + 2 * FSTG + ar1 * 40 + ao1, Bhi + (size_t)(col0 + ar1) * K + k0 + ao1);
        cp16(base + 3 * FSTG + ar0 * 40 + ao0, Blo + (size_t)(col0 + ar0) * K + k0 + ao0);
        cp16(base + 3 * FSTG + ar1 * 40 + ao1, Blo + (size_t)(col0 + ar1) * K + k0 + ao1);
        cp_commit();
    };

    issue(0, 0);

#pragma unroll 1
    for (int it = 0; it < niter; it++) {
        const int buf = it & 1;
        cp_wait0();
        __syncthreads();
        if (it + 1 < niter) issue(it + 1, buf ^ 1);
        const unsigned ahB = sbase + (buf * 4 * FSTG) * 2;
        const unsigned alB = ahB + FSTG * 2;
        const unsigned bhB = ahB + 2 * FSTG * 2;
        const unsigned blB = ahB + 3 * FSTG * 2;

#pragma unroll
        for (int kk = 0; kk < 32; kk += 16) {
            unsigned ah[4][4], bh[4][2], bl[4][2], al[4][4];
#pragma unroll
            for (int im = 0; im < 4; im++)
                ldsm_x4(ah[im][0], ah[im][1], ah[im][2], ah[im][3],
                        ahB + ((wm * 64 + im * 16 + la_row) * 40 + kk + la_k) * 2);
#pragma unroll
            for (int in_ = 0; in_ < 4; in_++)
                ldsm_x2(bh[in_][0], bh[in_][1],
                        bhB + ((wn * 32 + in_ * 8 + lb_row) * 40 + kk + lb_k) * 2);
#pragma unroll
            for (int im = 0; im < 4; im++)
#pragma unroll
                for (int in_ = 0; in_ < 4; in_++)
                    mma16816(acc[im][in_], ah[im][0], ah[im][1], ah[im][2], ah[im][3],
                             bh[in_][0], bh[in_][1]);
#pragma unroll
            for (int in_ = 0; in_ < 4; in_++)
                ldsm_x2(bl[in_][0], bl[in_][1],
                        blB + ((wn * 32 + in_ * 8 + lb_row) * 40 + kk + lb_k) * 2);
#pragma unroll
            for (int im = 0; im < 4; im++)
#pragma unroll
                for (int in_ = 0; in_ < 4; in_++)
                    mma16816(acc[im][in_], ah[im][0], ah[im][1], ah[im][2], ah[im][3],
                             bl[in_][0], bl[in_][1]);
#pragma unroll
            for (int im = 0; im < 4; im++)
                ldsm_x4(al[im][0], al[im][1], al[im][2], al[im][3],
                        alB + ((wm * 64 + im * 16 + la_row) * 40 + kk + la_k) * 2);
#pragma unroll
            for (int im = 0; im < 4; im++)
#pragma unroll
                for (int in_ = 0; in_ < 4; in_++)
                    mma16816(acc[im][in_], al[im][0], al[im][1], al[im][2], al[im][3],
                             bh[in_][0], bh[in_][1]);
        }
    }

#pragma unroll
    for (int im = 0; im < 4; im++) {
#pragma unroll
        for (int in_ = 0; in_ < 4; in_++) {
            int rr = row0 + wm * 64 + im * 16 + g;
            int cn = col0 + wn * 32 + in_ * 8 + tg * 2;
            float b0v = bias ? bias[cn] : 0.f;
            float b1v = bias ? bias[cn + 1] : 0.f;
#pragma unroll
            for (int half = 0; half < 2; half++) {
                int r = rr + half * 8;
                size_t orow;
                if (perm) {
                    int t = r >> 6, b = r & 63;
                    orow = (size_t)(b * Tt + t);
                } else {
                    orow = (size_t)r;
                }
                float2 v;
                v.x = acc[im][in_][half * 2 + 0] + b0v;
                v.y = acc[im][in_][half * 2 + 1] + b1v;
                *(float2*)(out + orow * N + cn) = v;
            }
        }
    }
}

// ---------------- wavefront LSTM cell: dual wg split-K, 1 barrier/iter ----------
#define WLD 40
#define WSTG (64 * WLD)
__global__ __launch_bounds__(256) void lstm_wave_mma_k(CellArgs args, int s) {
    extern __shared__ __nv_bfloat16 smem[];
    float* Zs = (float*)(smem + 16 * WSTG);       // [64][68]
    const unsigned sbase = (unsigned)__cvta_generic_to_shared(smem);

    const int tid  = threadIdx.x;
    const int wg   = tid >> 7;
    const int wtid = tid & 127;
    __nv_bfloat16* wgbase = smem + wg * 8 * WSTG;
    const unsigned wgB = sbase + (wg * 8 * WSTG) * 2;

    const int lmin = (s > 63) ? (s - 63) : 0;
    const int l    = lmin + blockIdx.y;
    const int t    = s - l;
    const size_t SH = (size_t)Bb * Hh;
    const int pin  = t & 1, pout = (t + 1) & 1;
    const int j0   = blockIdx.x * 16;

    const __nv_bfloat16* h_hi = g_hsp_hi + (size_t)(l * 2 + pin) * SH;
    const __nv_bfloat16* h_lo = g_hsp_lo + (size_t)(l * 2 + pin) * SH;
    const __nv_bfloat16* Uhi  = g_Usp_hi + (size_t)l * WHH;
    const __nv_bfloat16* Ulo  = g_Usp_lo + (size_t)l * WHH;

    const __nv_bfloat16 *Ah_, *Al_, *Bh_, *Bl_;
    int niter, kbase;
    if (l == 0) {
        Ah_ = h_hi; Al_ = h_lo; Bh_ = Uhi; Bl_ = Ulo;
        niter = 16; kbase = wg * 512;
    } else if (wg == 0) {
        Ah_ = g_hsp_hi + (size_t)((l - 1) * 2 + pout) * SH;
        Al_ = g_hsp_lo + (size_t)((l - 1) * 2 + pout) * SH;
        Bh_ = g_Wsp_hi + (size_t)(l - 1) * WHH;
        Bl_ = g_Wsp_lo + (size_t)(l - 1) * WHH;
        niter = 32; kbase = 0;
    } else {
        Ah_ = h_hi; Al_ = h_lo; Bh_ = Uhi; Bl_ = Ulo;
        niter = 32; kbase = 0;
    }
    const int bid  = wg + 1;

    const int wn   = wtid >> 5;
    const int lane = tid & 31;
    const int g    = lane >> 2, tg = lane & 3;

    const int la_row = lane & 15;
    const int la_k   = (lane >> 4) * 8;
    const int lb_row = lane & 7;
    const int lb_k   = ((lane >> 3) & 1) * 8;

    // cp coords: tile 64 rows x 32 k; 2 threads/row, 2x16B each
    const int arow = wtid >> 1;
    const int aoff = (wtid & 1) * 16;
    const int bgrow = (arow >> 4) * Hh + j0 + (arow & 15);

    float acc[4][2][4];
#pragma unroll
    for (int im = 0; im < 4; im++)
#pragma unroll
        for (int in_ = 0; in_ < 2; in_++)
#pragma unroll
            for (int q = 0; q < 4; q++) acc[im][in_][q] = 0.f;

    auto issue = [&](int i, int buf) {
        int k0 = kbase + i * 32;
        __nv_bfloat16* base = wgbase + buf * 4 * WSTG;
        cp16(base + arow * WLD + aoff,            Ah_ + (size_t)arow * Hh + k0 + aoff);
        cp16(base + arow * WLD + aoff + 8,        Ah_ + (size_t)arow * Hh + k0 + aoff + 8);
        cp16(base + WSTG + arow * WLD + aoff,     Al_ + (size_t)arow * Hh + k0 + aoff);
        cp16(base + WSTG + arow * WLD + aoff + 8, Al_ + (size_t)arow * Hh + k0 + aoff + 8);
        cp16(base + 2 * WSTG + arow * WLD + aoff,     Bh_ + (size_t)bgrow * Hh + k0 + aoff);
        cp16(base + 2 * WSTG + arow * WLD + aoff + 8, Bh_ + (size_t)bgrow * Hh + k0 + aoff + 8);
        cp16(base + 3 * WSTG + arow * WLD + aoff,     Bl_ + (size_t)bgrow * Hh + k0 + aoff);
        cp16(base + 3 * WSTG + arow * WLD + aoff + 8, Bl_ + (size_t)bgrow * Hh + k0 + aoff + 8);
        cp_commit();
    };

    issue(0, 0);

#pragma unroll 1
    for (int i = 0; i < niter; i++) {
        const int buf = i & 1;
        cp_wait0();
        barw(bid);
        if (i + 1 < niter) issue(i + 1, buf ^ 1);
        const unsigned ahB = wgB + (buf * 4 * WSTG) * 2;
        const unsigned alB = ahB + WSTG * 2;
        const unsigned bhB = ahB + 2 * WSTG * 2;
        const unsigned blB = ahB + 3 * WSTG * 2;

#pragma unroll
        for (int kk = 0; kk < 32; kk += 16) {
            unsigned ah[4][4], bh[2][2], bl[2][2], al[4][4];
#pragma unroll
            for (int im = 0; im < 4; im++)
                ldsm_x4(ah[im][0], ah[im][1], ah[im][2], ah[im][3],
                        ahB + ((im * 16 + la_row) * WLD + kk + la_k) * 2);
#pragma unroll
            for (int in_ = 0; in_ < 2; in_++)
                ldsm_x2(bh[in_][0], bh[in_][1],
                        bhB + ((wn * 16 + in_ * 8 + lb_row) * WLD + kk + lb_k) * 2);
#pragma unroll
            for (int im = 0; im < 4; im++)
#pragma unroll
                for (int in_ = 0; in_ < 2; in_++)
                    mma16816(acc[im][in_], ah[im][0], ah[im][1], ah[im][2], ah[im][3],
                             bh[in_][0], bh[in_][1]);
#pragma unroll
            for (int in_ = 0; in_ < 2; in_++)
                ldsm_x2(bl[in_][0], bl[in_][1],
                        blB + ((wn * 16 + in_ * 8 + lb_row) * WLD + kk + lb_k) * 2);
#pragma unroll
            for (int im = 0; im < 4; im++)
#pragma unroll
                for (int in_ = 0; in_ < 2; in_++)
                    mma16816(acc[im][in_], ah[im][0], ah[im][1], ah[im][2], ah[im][3],
                             bl[in_][0], bl[in_][1]);
#pragma unroll
            for (int im = 0; im < 4; im++)
                ldsm_x4(al[im][0], al[im][1], al[im][2], al[im][3],
                        alB + ((im * 16 + la_row) * WLD + kk + la_k) * 2);
#pragma unroll
            for (int im = 0; im < 4; im++)
#pragma unroll
                for (int in_ = 0; in_ < 2; in_++)
                    mma16816(acc[im][in_], al[im][0], al[im][1], al[im][2], al[im][3],
                             bh[in_][0], bh[in_][1]);
        }
    }

    // combine the two warpgroups' partial sums via Zs
    __syncthreads();
    if (wg == 0) {
#pragma unroll
        for (int im = 0; im < 4; im++)
#pragma unroll
            for (int in_ = 0; in_ < 2; in_++)
#pragma unroll
                for (int q = 0; q < 4; q++) {
                    int r = im * 16 + g + ((q >> 1) << 3);
                    int n = wn * 16 + in_ * 8 + tg * 2 + (q & 1);
                    Zs[r * 68 + n] = acc[im][in_][q];
                }
    }
    __syncthreads();
    if (wg == 1) {
#pragma unroll
        for (int im = 0; im < 4; im++)
#pragma unroll
            for (int in_ = 0; in_ < 2; in_++)
#pragma unroll
                for (int q = 0; q < 4; q++) {
                    int r = im * 16 + g + ((q >> 1) << 3);
                    int n = wn * 16 + in_ * 8 + tg * 2 + (q & 1);
                    Zs[r * 68 + n] += acc[im][in_][q];
                }
    }
    __syncthreads();

    const float* bias = args.b[l];
    float* c = g_c + (size_t)l * SH;
    __nv_bfloat16* ho_hi = g_hsp_hi + (size_t)(l * 2 + pout) * SH;
    __nv_bfloat16* ho_lo = g_hsp_lo + (size_t)(l * 2 + pout) * SH;
    const float* zp = (l == 0) ? (g_zpre + (size_t)t * Bb * 4 * Hh) : nullptr;

#pragma unroll
    for (int q = 0; q < 4; q++) {
        int e  = tid + 256 * q;
        int r  = e >> 4;
        int uu = e & 15;
        int j  = j0 + uu;
        float zi = Zs[r * 68 + uu]      + bias[j];
        float zf = Zs[r * 68 + 16 + uu] + bias[Hh + j];
        float zg = Zs[r * 68 + 32 + uu] + bias[2 * Hh + j];
        float zo = Zs[r * 68 + 48 + uu] + bias[3 * Hh + j];
        if (zp) {
            const float* z = zp + (size_t)r * (4 * Hh);
            zi += z[j]; zf += z[Hh + j]; zg += z[2 * Hh + j]; zo += z[3 * Hh + j];
        }
        float si = 1.f / (1.f + __expf(-zi));
        float sf = 1.f / (1.f + __expf(-zf));
        float so = 1.f / (1.f + __expf(-zo));
        float tg_ = tanhf(zg);
        float cn = sf * c[r * Hh + j] + si * tg_;
        float hn = so * tanhf(cn);
        c[r * Hh + j] = cn;
        __nv_bfloat16 hh = __float2bfloat16(hn);
        float lo = hn - __bfloat162float(hh);
        ho_hi[r * Hh + j] = hh;
        ho_lo[r * Hh + j] = __float2bfloat16(lo);
        if (l == 3) {
            size_t o = ((size_t)t * Bb + r) * Hh + j;
            g_Ahi[o] = hh;
            g_Alo[o] = __float2bfloat16(lo);
        }
    }
}

// ---------------- online softmax, chunked over t, float4 ------------------------
__global__ __launch_bounds__(256) void softmax_k(float* __restrict__ out, int t0) {
    __shared__ float mred[256], sred[256];
    int row = (blockIdx.x >> 3) * Tt + t0 + (blockIdx.x & 7);
    float4* p4 = (float4*)(out + (size_t)row * Vv);
    int tid = threadIdx.x;
    const int n4 = Vv / 4;

    float m = -3.4e38f, sum = 0.f;
    for (int i = tid; i < n4; i += 256) {
        float4 x = p4[i];
        float mx = fmaxf(fmaxf(x.x, x.y), fmaxf(x.z, x.w));
        float mn = fmaxf(m, mx);
        sum = sum * __expf(m - mn)
            + __expf(x.x - mn) + __expf(x.y - mn)
            + __expf(x.z - mn) + __expf(x.w - mn);
        m = mn;
    }
    mred[tid] = m; sred[tid] = sum; __syncthreads();
    for (int st = 128; st > 0; st >>= 1) {
        if (tid < st) {
            float m2 = mred[tid + st], s2 = sred[tid + st];
            float mn = fmaxf(mred[tid], m2);
            sred[tid] = sred[tid] * __expf(mred[tid] - mn) + s2 * __expf(m2 - mn);
            mred[tid] = mn;
        }
        __syncthreads();
    }
    float M = mred[0];
    float inv = 1.f / sred[0];
    for (int i = tid; i < n4; i += 256) {
        float4 x = p4[i];
        x.x = __expf(x.x - M) * inv;
        x.y = __expf(x.y - M) * inv;
        x.z = __expf(x.z - M) * inv;
        x.w = __expf(x.w - M) * inv;
        p4[i] = x;
    }
}

// ---------------- launch ------------------------------------------------------
extern "C" void kernel_launch(void* const* d_in, const int* in_sizes, int n_in,
                              void* d_out, int out_size) {
    (void)in_sizes; (void)n_in; (void)out_size;
    const int*   tok = (const int*)d_in[0];
    const float* emb = (const float*)d_in[9];
    const float* W[4]; const float* U[4];
    CellArgs args;
    for (int l = 0; l < 4; l++) {
        W[l] = (const float*)d_in[10 + 3 * l];
        U[l] = (const float*)d_in[11 + 3 * l];
        args.b[l] = (const float*)d_in[12 + 3 * l];
    }
    const float* Wfc = (const float*)d_in[22];
    const float* bfc = (const float*)d_in[23];
    float* out = (float*)d_out;

    float *xbuf, *hbuf, *cbuf, *zpre;
    __nv_bfloat16 *Ahi, *Alo, *B1hi, *B1lo, *Bhi, *Blo, *Wsph, *Wspl, *Usph, *Uspl;
    cudaGetSymbolAddress((void**)&xbuf, g_xbuf);
    cudaGetSymbolAddress((void**)&hbuf, g_h);
    cudaGetSymbolAddress((void**)&cbuf, g_c);
    cudaGetSymbolAddress((void**)&zpre, g_zpre);
    cudaGetSymbolAddress((void**)&Ahi,  g_Ahi);
    cudaGetSymbolAddress((void**)&Alo,  g_Alo);
    cudaGetSymbolAddress((void**)&B1hi, g_B1hi);
    cudaGetSymbolAddress((void**)&B1lo, g_B1lo);
    cudaGetSymbolAddress((void**)&Bhi,  g_Bhi);
    cudaGetSymbolAddress((void**)&Blo,  g_Blo);
    cudaGetSymbolAddress((void**)&Wsph, g_Wsp_hi);
    cudaGetSymbolAddress((void**)&Wspl, g_Wsp_lo);
    cudaGetSymbolAddress((void**)&Usph, g_Usp_hi);
    cudaGetSymbolAddress((void**)&Uspl, g_Usp_lo);

    const int wvSmem = 16 * WSTG * 2 + 64 * 68 * 4;   // 99328 B
    const int fcSmem = 8 * FSTG * 2;                  // 81920 B
    cudaFuncSetAttribute(lstm_wave_mma_k,
                         cudaFuncAttributeMaxDynamicSharedMemorySize, wvSmem);
    cudaFuncSetAttribute(mma_gemm_k,
                         cudaFuncAttributeMaxDynamicSharedMemorySize, fcSmem);

    // streams + events (created once, first non-capture call)
    // s1 = high priority (wave critical path), s2 = low priority (FC/softmax fill)
    static cudaStream_t s1 = nullptr, s2 = nullptr;
    static cudaEvent_t evF, evP, evD[8], evW, evJ;
    if (!s1) {
        int loPri, hiPri;
        cudaDeviceGetStreamPriorityRange(&loPri, &hiPri);
        cudaStreamCreateWithPriority(&s1, cudaStreamNonBlocking, hiPri);
        cudaStreamCreateWithPriority(&s2, cudaStreamNonBlocking, loPri);
        cudaEventCreateWithFlags(&evF, cudaEventDisableTiming);
        cudaEventCreateWithFlags(&evP, cudaEventDisableTiming);
        for (int k = 0; k < 8; k++)
            cudaEventCreateWithFlags(&evD[k], cudaEventDisableTiming);
        cudaEventCreateWithFlags(&evW, cudaEventDisableTiming);
        cudaEventCreateWithFlags(&evJ, cudaEventDisableTiming);
    }

    const size_t SH = (size_t)Bb * Hh;

    for (int l = 0; l < 4; l++) {
        cudaMemcpyAsync(hbuf + (size_t)(l * 2) * SH, d_in[1 + 2 * l],
                        SH * sizeof(float), cudaMemcpyDeviceToDevice, 0);
        cudaMemcpyAsync(cbuf + (size_t)l * SH, d_in[2 + 2 * l],
                        SH * sizeof(float), cudaMemcpyDeviceToDevice, 0);
    }

    // fork low-priority stream: Wfc transpose+split overlaps everything below
    cudaEventRecord(evF, 0);
    cudaStreamWaitEvent(s2, evF, 0);
    tsplit_k<<<dim3(Hh / 32, Vv / 32), 256, 0, s2>>>(Wfc, Bhi, Blo, Hh, Vv);

    embed_k<<<(Tt * Bb * Ee) / 256, 256>>>(tok, emb);
    hinit_split_k<<<(4 * Bb * Hh) / 256, 256>>>();

    // zpre = x @ W1 on tensor cores
    split_k<<<(4096 * 512) / 256, 256>>>(xbuf, Ahi, Alo, 4096 * 512);
    tsplit_k<<<dim3(Ee / 32, (4 * Hh) / 32), 256>>>(W[0], B1hi, B1lo, Ee, 4 * Hh);
    mma_gemm_k<<<dim3(32, (4 * Hh) / 128), 256, fcSmem>>>(
        Ahi, Alo, B1hi, B1lo, nullptr, zpre, Ee, 4 * Hh, 0, 0);

    // transpose+split recurrent weights
    for (int l = 1; l < 4; l++)
        tsplit_k<<<dim3(Hh / 32, (4 * Hh) / 32), 256>>>(
            W[l], Wsph + (size_t)(l - 1) * WHH, Wspl + (size_t)(l - 1) * WHH,
            Hh, 4 * Hh);
    for (int l = 0; l < 4; l++)
        tsplit_k<<<dim3(Hh / 32, (4 * Hh) / 32), 256>>>(
            U[l], Usph + (size_t)l * WHH, Uspl + (size_t)l * WHH, Hh, 4 * Hh);

    // wave on high-priority stream s1
    cudaEventRecord(evP, 0);
    cudaStreamWaitEvent(s1, evP, 0);
    for (int s = 0; s <= Tt + 3 - 1; s++) {
        int lmin = (s > Tt - 1) ? (s - (Tt - 1)) : 0;
        int lmax = (s < 3) ? s : 3;
        int ny   = lmax - lmin + 1;
        lstm_wave_mma_k<<<dim3(Hh / 16, ny), 256, wvSmem, s1>>>(args, s);
        // h4 rows for t in [8k, 8k+8) complete at diagonal 8k+10
        if (s >= 10 && s <= 66 && ((s - 10) & 7) == 0)
            cudaEventRecord(evD[(s - 10) >> 3], s1);
    }
    cudaEventRecord(evW, s1);

    // FC + softmax in 8 row-chunks on the low-priority stream
    for (int k = 0; k < 8; k++) {
        cudaStreamWaitEvent(s2, evD[k], 0);
        mma_gemm_k<<<dim3(4, Vv / 128), 256, fcSmem, s2>>>(
            Ahi, Alo, Bhi, Blo, bfc, out, Hh, Vv, 1, k * 512);
        softmax_k<<<Bb * 8, 256, 0, s2>>>(out, k * 8);
    }
    cudaEventRecord(evJ, s2);
    cudaStreamWaitEvent(0, evJ, 0);
    cudaStreamWaitEvent(0, evW, 0);
}

// round 13
// speedup vs baseline: 1.0455x; 1.0455x over previous
#include <cuda_runtime.h>
#include <cuda_bf16.h>

#define Bb 64
#define Tt 64
#define Hh 1024
#define Vv 32000
#define Ee 512
#define WHH (4 * Hh * Hh)

// ---------------- scratch (static device memory; no allocation) ----------------
__device__ float g_xbuf[Tt * Bb * Ee];
__device__ float g_h[8 * Bb * Hh];
__device__ float g_c[4 * Bb * Hh];
__device__ float g_zpre[Tt * Bb * 4 * Hh];
__device__ __nv_bfloat16 g_Ahi[4096 * 1024];
__device__ __nv_bfloat16 g_Alo[4096 * 1024];
__device__ __nv_bfloat16 g_B1hi[4096 * 512];
__device__ __nv_bfloat16 g_B1lo[4096 * 512];
__device__ __nv_bfloat16 g_Bhi[(size_t)Vv * 1024];
__device__ __nv_bfloat16 g_Blo[(size_t)Vv * 1024];
__device__ __nv_bfloat16 g_hsp_hi[8 * Bb * Hh];
__device__ __nv_bfloat16 g_hsp_lo[8 * Bb * Hh];
__device__ __nv_bfloat16 g_Wsp_hi[3 * WHH];
__device__ __nv_bfloat16 g_Wsp_lo[3 * WHH];
__device__ __nv_bfloat16 g_Usp_hi[4 * WHH];
__device__ __nv_bfloat16 g_Usp_lo[4 * WHH];

struct CellArgs {
    const float* b[4];
};

// ---------------- cp.async / ldmatrix / mma helpers -----------------------------
__device__ __forceinline__ void cp16(void* smem_dst, const void* gsrc) {
    unsigned s = (unsigned)__cvta_generic_to_shared(smem_dst);
    asm volatile("cp.async.cg.shared.global [%0], [%1], 16;\n" :: "r"(s), "l"(gsrc));
}
__device__ __forceinline__ void cp_commit() {
    asm volatile("cp.async.commit_group;\n" ::: "memory");
}
__device__ __forceinline__ void cp_wait1() {
    asm volatile("cp.async.wait_group 1;\n" ::: "memory");
}
__device__ __forceinline__ void cp_wait0() {
    asm volatile("cp.async.wait_group 0;\n" ::: "memory");
}
__device__ __forceinline__ void barw(int id) {
    asm volatile("bar.sync %0, 128;" :: "r"(id) : "memory");
}

__device__ __forceinline__ void ldsm_x4(unsigned& r0, unsigned& r1, unsigned& r2,
                                        unsigned& r3, unsigned addr) {
    asm volatile("ldmatrix.sync.aligned.m8n8.x4.shared.b16 {%0,%1,%2,%3}, [%4];"
                 : "=r"(r0), "=r"(r1), "=r"(r2), "=r"(r3) : "r"(addr));
}
__device__ __forceinline__ void ldsm_x2(unsigned& r0, unsigned& r1, unsigned addr) {
    asm volatile("ldmatrix.sync.aligned.m8n8.x2.shared.b16 {%0,%1}, [%2];"
                 : "=r"(r0), "=r"(r1) : "r"(addr));
}

__device__ __forceinline__ void mma16816(float c[4],
                                         unsigned a0, unsigned a1, unsigned a2, unsigned a3,
                                         unsigned b0, unsigned b1) {
    asm volatile(
        "mma.sync.aligned.m16n8k16.row.col.f32.bf16.bf16.f32 "
        "{%0,%1,%2,%3}, {%4,%5,%6,%7}, {%8,%9}, {%0,%1,%2,%3};"
        : "+f"(c[0]), "+f"(c[1]), "+f"(c[2]), "+f"(c[3])
        : "r"(a0), "r"(a1), "r"(a2), "r"(a3), "r"(b0), "r"(b1));
}

// ---------------- embedding lookup ---------------------------------------------
__global__ __launch_bounds__(256) void embed_k(const int* __restrict__ tok,
                                               const float* __restrict__ emb) {
    int idx = blockIdx.x * 256 + threadIdx.x;
    int e  = idx & (Ee - 1);
    int bt = idx >> 9;
    int b  = bt & (Bb - 1);
    int t  = bt >> 6;
    g_xbuf[idx] = emb[(size_t)tok[b * Tt + t] * Ee + e];
}

// ---------------- fp32 -> (hi, lo) bf16 split ----------------------------------
__global__ __launch_bounds__(256) void split_k(const float* __restrict__ src,
                                               __nv_bfloat16* __restrict__ hi,
                                               __nv_bfloat16* __restrict__ lo, int n) {
    int i = blockIdx.x * 256 + threadIdx.x;
    if (i < n) {
        float x = src[i];
        __nv_bfloat16 h = __float2bfloat16(x);
        hi[i] = h;
        lo[i] = __float2bfloat16(x - __bfloat162float(h));
    }
}

// ---------------- split initial h states ---------------------------------------
__global__ __launch_bounds__(256) void hinit_split_k() {
    int i = blockIdx.x * 256 + threadIdx.x;
    int l = i >> 16;
    int r = i & 65535;
    size_t o = ((size_t)(l * 2)) * (Bb * Hh) + r;
    float x = g_h[o];
    __nv_bfloat16 h = __float2bfloat16(x);
    g_hsp_hi[o] = h;
    g_hsp_lo[o] = __float2bfloat16(x - __bfloat162float(h));
}

// ---------------- transpose + split: src[K][N] -> hi/lo [N][K] ------------------
__global__ __launch_bounds__(256) void tsplit_k(const float* __restrict__ src,
                                                __nv_bfloat16* __restrict__ hi,
                                                __nv_bfloat16* __restrict__ lo,
                                                int K, int N) {
    __shared__ float tile[32][33];
    int k0 = blockIdx.x * 32, n0 = blockIdx.y * 32;
    int tx = threadIdx.x & 31, ty = threadIdx.x >> 5;
#pragma unroll
    for (int j = 0; j < 32; j += 8)
        tile[ty + j][tx] = src[(size_t)(k0 + ty + j) * N + n0 + tx];
    __syncthreads();
#pragma unroll
    for (int j = 0; j < 32; j += 8) {
        float x = tile[tx][ty + j];
        __nv_bfloat16 h = __float2bfloat16(x);
        size_t o = (size_t)(n0 + ty + j) * K + k0 + tx;
        hi[o] = h;
        lo[o] = __float2bfloat16(x - __bfloat162float(h));
    }
}

// ---------------- split-bf16 tensor-core GEMM, fused 3-pass + ldmatrix ----------
// (round-10 known-good: issue(i+1) -> wait1 -> sync -> compute -> sync)
#define FSTG (128 * 40)
__global__ __launch_bounds__(256) void mma_gemm_k(
    const __nv_bfloat16* __restrict__ Ahi, const __nv_bfloat16* __restrict__ Alo,
    const __nv_bfloat16* __restrict__ Bhi, const __nv_bfloat16* __restrict__ Blo,
    const float* __restrict__ bias,
    float* __restrict__ out, int K, int N, int perm, int rowbase)
{
    extern __shared__ __nv_bfloat16 fsm[];
    const unsigned sbase = (unsigned)__cvta_generic_to_shared(fsm);

    const int tid  = threadIdx.x;
    const int row0 = rowbase + blockIdx.x * 128;
    const int col0 = blockIdx.y * 128;
    const int wid  = tid >> 5, lane = tid & 31;
    const int wm   = wid >> 2;
    const int wn   = wid & 3;
    const int g    = lane >> 2, tg = lane & 3;

    const int la_row = lane & 15;
    const int la_k   = (lane >> 4) * 8;
    const int lb_row = lane & 7;
    const int lb_k   = ((lane >> 3) & 1) * 8;

    const int niter = K >> 5;

    float acc[4][4][4];
#pragma unroll
    for (int im = 0; im < 4; im++)
#pragma unroll
        for (int in_ = 0; in_ < 4; in_++)
#pragma unroll
            for (int q = 0; q < 4; q++) acc[im][in_][q] = 0.f;

    const int ca  = tid * 2;
    const int ar0 = ca >> 2,       ao0 = (ca & 3) * 8;
    const int ar1 = (ca + 1) >> 2, ao1 = ((ca + 1) & 3) * 8;

    auto issue = [&](int it, int buf) {
        int k0 = it * 32;
        __nv_bfloat16* base = fsm + buf * 4 * FSTG;
        cp16(base + ar0 * 40 + ao0,            Ahi + (size_t)(row0 + ar0) * K + k0 + ao0);
        cp16(base + ar1 * 40 + ao1,            Ahi + (size_t)(row0 + ar1) * K + k0 + ao1);
        cp16(base + FSTG + ar0 * 40 + ao0,     Alo + (size_t)(row0 + ar0) * K + k0 + ao0);
        cp16(base + FSTG + ar1 * 40 + ao1,     Alo + (size_t)(row0 + ar1) * K + k0 + ao1);
        cp16(base + 2 * FSTG + ar0 * 40 + ao0, Bhi + (size_t)(col0 + ar0) * K + k0 + ao0);
        cp16(base + 2 * FSTG + ar1 * 40 + ao1, Bhi + (size_t)(col0 + ar1) * K + k0 + ao1);
        cp16(base + 3 * FSTG + ar0 * 40 + ao0, Blo + (size_t)(col0 + ar0) * K + k0 + ao0);
        cp16(base + 3 * FSTG + ar1 * 40 + ao1, Blo + (size_t)(col0 + ar1) * K + k0 + ao1);
        cp_commit();
    };

    issue(0, 0);

#pragma unroll 1
    for (int it = 0; it < niter; it++) {
        const int buf = it & 1;
        if (it + 1 < niter) { issue(it + 1, buf ^ 1); cp_wait1(); }
        else                { cp_wait0(); }
        __syncthreads();
        const unsigned ahB = sbase + (buf * 4 * FSTG) * 2;
        const unsigned alB = ahB + FSTG * 2;
        const unsigned bhB = ahB + 2 * FSTG * 2;
        const unsigned blB = ahB + 3 * FSTG * 2;

#pragma unroll
        for (int kk = 0; kk < 32; kk += 16) {
            unsigned ah[4][4], bh[4][2], bl[4][2], al[4][4];
#pragma unroll
            for (int im = 0; im < 4; im++)
                ldsm_x4(ah[im][0], ah[im][1], ah[im][2], ah[im][3],
                        ahB + ((wm * 64 + im * 16 + la_row) * 40 + kk + la_k) * 2);
#pragma unroll
            for (int in_ = 0; in_ < 4; in_++)
                ldsm_x2(bh[in_][0], bh[in_][1],
                        bhB + ((wn * 32 + in_ * 8 + lb_row) * 40 + kk + lb_k) * 2);
#pragma unroll
            for (int im = 0; im < 4; im++)
#pragma unroll
                for (int in_ = 0; in_ < 4; in_++)
                    mma16816(acc[im][in_], ah[im][0], ah[im][1], ah[im][2], ah[im][3],
                             bh[in_][0], bh[in_][1]);
#pragma unroll
            for (int in_ = 0; in_ < 4; in_++)
                ldsm_x2(bl[in_][0], bl[in_][1],
                        blB + ((wn * 32 + in_ * 8 + lb_row) * 40 + kk + lb_k) * 2);
#pragma unroll
            for (int im = 0; im < 4; im++)
#pragma unroll
                for (int in_ = 0; in_ < 4; in_++)
                    mma16816(acc[im][in_], ah[im][0], ah[im][1], ah[im][2], ah[im][3],
                             bl[in_][0], bl[in_][1]);
#pragma unroll
            for (int im = 0; im < 4; im++)
                ldsm_x4(al[im][0], al[im][1], al[im][2], al[im][3],
                        alB + ((wm * 64 + im * 16 + la_row) * 40 + kk + la_k) * 2);
#pragma unroll
            for (int im = 0; im < 4; im++)
#pragma unroll
                for (int in_ = 0; in_ < 4; in_++)
                    mma16816(acc[im][in_], al[im][0], al[im][1], al[im][2], al[im][3],
                             bh[in_][0], bh[in_][1]);
        }
        __syncthreads();
    }

#pragma unroll
    for (int im = 0; im < 4; im++) {
#pragma unroll
        for (int in_ = 0; in_ < 4; in_++) {
            int rr = row0 + wm * 64 + im * 16 + g;
            int cn = col0 + wn * 32 + in_ * 8 + tg * 2;
            float b0v = bias ? bias[cn] : 0.f;
            float b1v = bias ? bias[cn + 1] : 0.f;
#pragma unroll
            for (int half = 0; half < 2; half++) {
                int r = rr + half * 8;
                size_t orow;
                if (perm) {
                    int t = r >> 6, b = r & 63;
                    orow = (size_t)(b * Tt + t);
                } else {
                    orow = (size_t)r;
                }
                float2 v;
                v.x = acc[im][in_][half * 2 + 0] + b0v;
                v.y = acc[im][in_][half * 2 + 1] + b1v;
                *(float2*)(out + orow * N + cn) = v;
            }
        }
    }
}

// ---------------- wavefront LSTM cell (round-10 known-good) ---------------------
#define WLD 40
#define WSTG (64 * WLD)
__global__ __launch_bounds__(256) void lstm_wave_mma_k(CellArgs args, int s) {
    extern __shared__ __nv_bfloat16 smem[];
    float* Zs = (float*)(smem + 16 * WSTG);       // [64][68]
    const unsigned sbase = (unsigned)__cvta_generic_to_shared(smem);

    const int tid  = threadIdx.x;
    const int wg   = tid >> 7;
    const int wtid = tid & 127;
    __nv_bfloat16* wgbase = smem + wg * 8 * WSTG;
    const unsigned wgB = sbase + (wg * 8 * WSTG) * 2;

    const int lmin = (s > 63) ? (s - 63) : 0;
    const int l    = lmin + blockIdx.y;
    const int t    = s - l;
    const size_t SH = (size_t)Bb * Hh;
    const int pin  = t & 1, pout = (t + 1) & 1;
    const int j0   = blockIdx.x * 16;

    const __nv_bfloat16* h_hi = g_hsp_hi + (size_t)(l * 2 + pin) * SH;
    const __nv_bfloat16* h_lo = g_hsp_lo + (size_t)(l * 2 + pin) * SH;
    const __nv_bfloat16* Uhi  = g_Usp_hi + (size_t)l * WHH;
    const __nv_bfloat16* Ulo  = g_Usp_lo + (size_t)l * WHH;

    const __nv_bfloat16 *Ah_, *Al_, *Bh_, *Bl_;
    int niter, kbase;
    if (l == 0) {
        Ah_ = h_hi; Al_ = h_lo; Bh_ = Uhi; Bl_ = Ulo;
        niter = 16; kbase = wg * 512;
    } else if (wg == 0) {
        Ah_ = g_hsp_hi + (size_t)((l - 1) * 2 + pout) * SH;
        Al_ = g_hsp_lo + (size_t)((l - 1) * 2 + pout) * SH;
        Bh_ = g_Wsp_hi + (size_t)(l - 1) * WHH;
        Bl_ = g_Wsp_lo + (size_t)(l - 1) * WHH;
        niter = 32; kbase = 0;
    } else {
        Ah_ = h_hi; Al_ = h_lo; Bh_ = Uhi; Bl_ = Ulo;
        niter = 32; kbase = 0;
    }
    const int bid  = wg + 1;

    const int wn   = wtid >> 5;
    const int lane = tid & 31;
    const int g    = lane >> 2, tg = lane & 3;

    const int la_row = lane & 15;
    const int la_k   = (lane >> 4) * 8;
    const int lb_row = lane & 7;
    const int lb_k   = ((lane >> 3) & 1) * 8;

    const int arow = wtid >> 1;
    const int aoff = (wtid & 1) * 16;
    const int bgrow = (arow >> 4) * Hh + j0 + (arow & 15);

    float acc[4][2][4];
#pragma unroll
    for (int im = 0; im < 4; im++)
#pragma unroll
        for (int in_ = 0; in_ < 2; in_++)
#pragma unroll
            for (int q = 0; q < 4; q++) acc[im][in_][q] = 0.f;

    auto issue = [&](int i, int buf) {
        int k0 = kbase + i * 32;
        __nv_bfloat16* base = wgbase + buf * 4 * WSTG;
        cp16(base + arow * WLD + aoff,            Ah_ + (size_t)arow * Hh + k0 + aoff);
        cp16(base + arow * WLD + aoff + 8,        Ah_ + (size_t)arow * Hh + k0 + aoff + 8);
        cp16(base + WSTG + arow * WLD + aoff,     Al_ + (size_t)arow * Hh + k0 + aoff);
        cp16(base + WSTG + arow * WLD + aoff + 8, Al_ + (size_t)arow * Hh + k0 + aoff + 8);
        cp16(base + 2 * WSTG + arow * WLD + aoff,     Bh_ + (size_t)bgrow * Hh + k0 + aoff);
        cp16(base + 2 * WSTG + arow * WLD + aoff + 8, Bh_ + (size_t)bgrow * Hh + k0 + aoff + 8);
        cp16(base + 3 * WSTG + arow * WLD + aoff,     Bl_ + (size_t)bgrow * Hh + k0 + aoff);
        cp16(base + 3 * WSTG + arow * WLD + aoff + 8, Bl_ + (size_t)bgrow * Hh + k0 + aoff + 8);
        cp_commit();
    };

    issue(0, 0);

#pragma unroll 1
    for (int i = 0; i < niter; i++) {
        const int buf = i & 1;
        if (i + 1 < niter) { issue(i + 1, buf ^ 1); cp_wait1(); }
        else               { cp_wait0(); }
        barw(bid);
        const unsigned ahB = wgB + (buf * 4 * WSTG) * 2;
        const unsigned alB = ahB + WSTG * 2;
        const unsigned bhB = ahB + 2 * WSTG * 2;
        const unsigned blB = ahB + 3 * WSTG * 2;

#pragma unroll
        for (int kk = 0; kk < 32; kk += 16) {
            unsigned ah[4][4], bh[2][2], bl[2][2], al[4][4];
#pragma unroll
            for (int im = 0; im < 4; im++)
                ldsm_x4(ah[im][0], ah[im][1], ah[im][2], ah[im][3],
                        ahB + ((im * 16 + la_row) * WLD + kk + la_k) * 2);
#pragma unroll
            for (int in_ = 0; in_ < 2; in_++)
                ldsm_x2(bh[in_][0], bh[in_][1],
                        bhB + ((wn * 16 + in_ * 8 + lb_row) * WLD + kk + lb_k) * 2);
#pragma unroll
            for (int im = 0; im < 4; im++)
#pragma unroll
                for (int in_ = 0; in_ < 2; in_++)
                    mma16816(acc[im][in_], ah[im][0], ah[im][1], ah[im][2], ah[im][3],
                             bh[in_][0], bh[in_][1]);
#pragma unroll
            for (int in_ = 0; in_ < 2; in_++)
                ldsm_x2(bl[in_][0], bl[in_][1],
                        blB + ((wn * 16 + in_ * 8 + lb_row) * WLD + kk + lb_k) * 2);
#pragma unroll
            for (int im = 0; im < 4; im++)
#pragma unroll
                for (int in_ = 0; in_ < 2; in_++)
                    mma16816(acc[im][in_], ah[im][0], ah[im][1], ah[im][2], ah[im][3],
                             bl[in_][0], bl[in_][1]);
#pragma unroll
            for (int im = 0; im < 4; im++)
                ldsm_x4(al[im][0], al[im][1], al[im][2], al[im][3],
                        alB + ((im * 16 + la_row) * WLD + kk + la_k) * 2);
#pragma unroll
            for (int im = 0; im < 4; im++)
#pragma unroll
                for (int in_ = 0; in_ < 2; in_++)
                    mma16816(acc[im][in_], al[im][0], al[im][1], al[im][2], al[im][3],
                             bh[in_][0], bh[in_][1]);
        }
        barw(bid);
    }

    // combine the two warpgroups' partial sums via Zs
    __syncthreads();
    if (wg == 0) {
#pragma unroll
        for (int im = 0; im < 4; im++)
#pragma unroll
            for (int in_ = 0; in_ < 2; in_++)
#pragma unroll
                for (int q = 0; q < 4; q++) {
                    int r = im * 16 + g + ((q >> 1) << 3);
                    int n = wn * 16 + in_ * 8 + tg * 2 + (q & 1);
                    Zs[r * 68 + n] = acc[im][in_][q];
                }
    }
    __syncthreads();
    if (wg == 1) {
#pragma unroll
        for (int im = 0; im < 4; im++)
#pragma unroll
            for (int in_ = 0; in_ < 2; in_++)
#pragma unroll
                for (int q = 0; q < 4; q++) {
                    int r = im * 16 + g + ((q >> 1) << 3);
                    int n = wn * 16 + in_ * 8 + tg * 2 + (q & 1);
                    Zs[r * 68 + n] += acc[im][in_][q];
                }
    }
    __syncthreads();

    const float* bias = args.b[l];
    float* c = g_c + (size_t)l * SH;
    __nv_bfloat16* ho_hi = g_hsp_hi + (size_t)(l * 2 + pout) * SH;
    __nv_bfloat16* ho_lo = g_hsp_lo + (size_t)(l * 2 + pout) * SH;
    const float* zp = (l == 0) ? (g_zpre + (size_t)t * Bb * 4 * Hh) : nullptr;

#pragma unroll
    for (int q = 0; q < 4; q++) {
        int e  = tid + 256 * q;
        int r  = e >> 4;
        int uu = e & 15;
        int j  = j0 + uu;
        float zi = Zs[r * 68 + uu]      + bias[j];
        float zf = Zs[r * 68 + 16 + uu] + bias[Hh + j];
        float zg = Zs[r * 68 + 32 + uu] + bias[2 * Hh + j];
        float zo = Zs[r * 68 + 48 + uu] + bias[3 * Hh + j];
        if (zp) {
            const float* z = zp + (size_t)r * (4 * Hh);
            zi += z[j]; zf += z[Hh + j]; zg += z[2 * Hh + j]; zo += z[3 * Hh + j];
        }
        float si = 1.f / (1.f + __expf(-zi));
        float sf = 1.f / (1.f + __expf(-zf));
        float so = 1.f / (1.f + __expf(-zo));
        float tg_ = tanhf(zg);
        float cn = sf * c[r * Hh + j] + si * tg_;
        float hn = so * tanhf(cn);
        c[r * Hh + j] = cn;
        __nv_bfloat16 hh = __float2bfloat16(hn);
        float lo = hn - __bfloat162float(hh);
        ho_hi[r * Hh + j] = hh;
        ho_lo[r * Hh + j] = __float2bfloat16(lo);
        if (l == 3) {
            size_t o = ((size_t)t * Bb + r) * Hh + j;
            g_Ahi[o] = hh;
            g_Alo[o] = __float2bfloat16(lo);
        }
    }
}

// ---------------- online softmax, chunked over t, float4 ------------------------
__global__ __launch_bounds__(256) void softmax_k(float* __restrict__ out, int t0) {
    __shared__ float mred[256], sred[256];
    int row = (blockIdx.x >> 3) * Tt + t0 + (blockIdx.x & 7);
    float4* p4 = (float4*)(out + (size_t)row * Vv);
    int tid = threadIdx.x;
    const int n4 = Vv / 4;

    float m = -3.4e38f, sum = 0.f;
    for (int i = tid; i < n4; i += 256) {
        float4 x = p4[i];
        float mx = fmaxf(fmaxf(x.x, x.y), fmaxf(x.z, x.w));
        float mn = fmaxf(m, mx);
        sum = sum * __expf(m - mn)
            + __expf(x.x - mn) + __expf(x.y - mn)
            + __expf(x.z - mn) + __expf(x.w - mn);
        m = mn;
    }
    mred[tid] = m; sred[tid] = sum; __syncthreads();
    for (int st = 128; st > 0; st >>= 1) {
        if (tid < st) {
            float m2 = mred[tid + st], s2 = sred[tid + st];
            float mn = fmaxf(mred[tid], m2);
            sred[tid] = sred[tid] * __expf(mred[tid] - mn) + s2 * __expf(m2 - mn);
            mred[tid] = mn;
        }
        __syncthreads();
    }
    float M = mred[0];
    float inv = 1.f / sred[0];
    for (int i = tid; i < n4; i += 256) {
        float4 x = p4[i];
        x.x = __expf(x.x - M) * inv;
        x.y = __expf(x.y - M) * inv;
        x.z = __expf(x.z - M) * inv;
        x.w = __expf(x.w - M) * inv;
        p4[i] = x;
    }
}

// ---------------- launch ------------------------------------------------------
extern "C" void kernel_launch(void* const* d_in, const int* in_sizes, int n_in,
                              void* d_out, int out_size) {
    (void)in_sizes; (void)n_in; (void)out_size;
    const int*   tok = (const int*)d_in[0];
    const float* emb = (const float*)d_in[9];
    const float* W[4]; const float* U[4];
    CellArgs args;
    for (int l = 0; l < 4; l++) {
        W[l] = (const float*)d_in[10 + 3 * l];
        U[l] = (const float*)d_in[11 + 3 * l];
        args.b[l] = (const float*)d_in[12 + 3 * l];
    }
    const float* Wfc = (const float*)d_in[22];
    const float* bfc = (const float*)d_in[23];
    float* out = (float*)d_out;

    float *xbuf, *hbuf, *cbuf, *zpre;
    __nv_bfloat16 *Ahi, *Alo, *B1hi, *B1lo, *Bhi, *Blo, *Wsph, *Wspl, *Usph, *Uspl;
    cudaGetSymbolAddress((void**)&xbuf, g_xbuf);
    cudaGetSymbolAddress((void**)&hbuf, g_h);
    cudaGetSymbolAddress((void**)&cbuf, g_c);
    cudaGetSymbolAddress((void**)&zpre, g_zpre);
    cudaGetSymbolAddress((void**)&Ahi,  g_Ahi);
    cudaGetSymbolAddress((void**)&Alo,  g_Alo);
    cudaGetSymbolAddress((void**)&B1hi, g_B1hi);
    cudaGetSymbolAddress((void**)&B1lo, g_B1lo);
    cudaGetSymbolAddress((void**)&Bhi,  g_Bhi);
    cudaGetSymbolAddress((void**)&Blo,  g_Blo);
    cudaGetSymbolAddress((void**)&Wsph, g_Wsp_hi);
    cudaGetSymbolAddress((void**)&Wspl, g_Wsp_lo);
    cudaGetSymbolAddress((void**)&Usph, g_Usp_hi);
    cudaGetSymbolAddress((void**)&Uspl, g_Usp_lo);

    const int wvSmem = 16 * WSTG * 2 + 64 * 68 * 4;   // 99328 B
    const int fcSmem = 8 * FSTG * 2;                  // 81920 B
    cudaFuncSetAttribute(lstm_wave_mma_k,
                         cudaFuncAttributeMaxDynamicSharedMemorySize, wvSmem);
    cudaFuncSetAttribute(mma_gemm_k,
                         cudaFuncAttributeMaxDynamicSharedMemorySize, fcSmem);

    // side stream + events: created once on the first (non-capture) call
    static cudaStream_t s2 = nullptr;
    static cudaEvent_t evF, evS, evD[8], evJ;
    if (!s2) {
        cudaStreamCreateWithFlags(&s2, cudaStreamNonBlocking);
        cudaEventCreateWithFlags(&evF, cudaEventDisableTiming);
        cudaEventCreateWithFlags(&evS, cudaEventDisableTiming);
        for (int k = 0; k < 8; k++)
            cudaEventCreateWithFlags(&evD[k], cudaEventDisableTiming);
        cudaEventCreateWithFlags(&evJ, cudaEventDisableTiming);
    }

    const size_t SH = (size_t)Bb * Hh;

    for (int l = 0; l < 4; l++) {
        cudaMemcpyAsync(hbuf + (size_t)(l * 2) * SH, d_in[1 + 2 * l],
                        SH * sizeof(float), cudaMemcpyDeviceToDevice, 0);
        cudaMemcpyAsync(cbuf + (size_t)l * SH, d_in[2 + 2 * l],
                        SH * sizeof(float), cudaMemcpyDeviceToDevice, 0);
    }

    // fork side stream: recurrent-weight tsplits run concurrently with the zpre
    // chain on the default stream; Wfc tsplit follows on s2 (needed only by FC)
    cudaEventRecord(evF, 0);
    cudaStreamWaitEvent(s2, evF, 0);
    for (int l = 1; l < 4; l++)
        tsplit_k<<<dim3(Hh / 32, (4 * Hh) / 32), 256, 0, s2>>>(
            W[l], Wsph + (size_t)(l - 1) * WHH, Wspl + (size_t)(l - 1) * WHH,
            Hh, 4 * Hh);
    for (int l = 0; l < 4; l++)
        tsplit_k<<<dim3(Hh / 32, (4 * Hh) / 32), 256, 0, s2>>>(
            U[l], Usph + (size_t)l * WHH, Uspl + (size_t)l * WHH, Hh, 4 * Hh);
    cudaEventRecord(evS, s2);
    tsplit_k<<<dim3(Hh / 32, Vv / 32), 256, 0, s2>>>(Wfc, Bhi, Blo, Hh, Vv);

    // default stream: embedding + zpre chain
    embed_k<<<(Tt * Bb * Ee) / 256, 256>>>(tok, emb);
    hinit_split_k<<<(4 * Bb * Hh) / 256, 256>>>();
    split_k<<<(4096 * 512) / 256, 256>>>(xbuf, Ahi, Alo, 4096 * 512);
    tsplit_k<<<dim3(Ee / 32, (4 * Hh) / 32), 256>>>(W[0], B1hi, B1lo, Ee, 4 * Hh);
    mma_gemm_k<<<dim3(32, (4 * Hh) / 128), 256, fcSmem>>>(
        Ahi, Alo, B1hi, B1lo, nullptr, zpre, Ee, 4 * Hh, 0, 0);

    // wave needs the recurrent-weight splits done
    cudaStreamWaitEvent(0, evS, 0);

    // wavefront over diagonals; FC+softmax chunks overlap on s2
    for (int s = 0; s <= Tt + 3 - 1; s++) {
        int lmin = (s > Tt - 1) ? (s - (Tt - 1)) : 0;
        int lmax = (s < 3) ? s : 3;
        int ny   = lmax - lmin + 1;
        lstm_wave_mma_k<<<dim3(Hh / 16, ny), 256, wvSmem>>>(args, s);
        // h4 rows for t in [8k, 8k+8) complete at diagonal 8k+10
        if (s >= 10 && s <= 66 && ((s - 10) & 7) == 0)
            cudaEventRecord(evD[(s - 10) >> 3], 0);
    }

    // FC + softmax in 8 row-chunks on the side stream
    for (int k = 0; k < 8; k++) {
        cudaStreamWaitEvent(s2, evD[k], 0);
        mma_gemm_k<<<dim3(4, Vv / 128), 256, fcSmem, s2>>>(
            Ahi, Alo, Bhi, Blo, bfc, out, Hh, Vv, 1, k * 512);
        softmax_k<<<Bb * 8, 256, 0, s2>>>(out, k * 8);
    }
    cudaEventRecord(evJ, s2);
    cudaStreamWaitEvent(0, evJ, 0);
}